// round 12
// baseline (speedup 1.0000x reference)
#include <cuda_runtime.h>

// RankingLoss: out = mean(1/(pred^2+eps)) + [ sum_{i:neg, j:pos} relu(pred_j - pred_i) ] / (n_neg*n_pos)
// DELTA = 0, EPS = 1e-5, B = 8192. target is int32 on the wire.
//
// Minimal-serial-chain O(B) design:
//   Phase A (32 blocks x 256): each thread bins its ONE element into a per-class
//     512-bin histogram with a single packed-u64 atomic:
//        packet = (1<<48) | (q + 2^23),  q = llrintf(p * 2^20)
//     (count in bits [48:64), biased fixed-point sum in [0:48) -- no carry possible).
//     Trivial term: warp shuffle-reduce -> one fixed-point u64 atomic per warp.
//   Ticket: last-arriving block alone computes
//        pair = sum_b negCnt[b]*posSumAbove(b) - negSum[b]*posCntAbove(b)
//     from the bin table (no second element pass), using a one-warp suffix scan
//     (16 bins/lane). n_pos/n_neg come from the histogram totals. Integer atomics
//     everywhere -> fully deterministic. All globals self-zero for graph replay.

#define BLOCK   256
#define GRID    32
#define BINS    512
#define QSCALE  1048576.0f             // 2^20
#define QINV_D  (1.0 / 1048576.0)
#define BIAS    (1ll << 23)
#define MASK48  ((1ull << 48) - 1ull)

__device__ unsigned long long g_posH[BINS];   // zero-init; last block re-zeros
__device__ unsigned long long g_negH[BINS];
__device__ unsigned long long g_trivq;        // fixed-point (2^20) trivial-term sum
__device__ unsigned int       g_tick;         // wraps to 0 every replay

__device__ __forceinline__ int bin_of(float p) {
    // 512 bins over [-5, 5): monotone => cross-bin pair classification exact.
    int b = (int)fmaf(p, 51.2f, 256.0f);
    return max(0, min(BINS - 1, b));
}

__global__ __launch_bounds__(BLOCK)
void rank_kernel(const float* __restrict__ pred,
                 const int* __restrict__ target,
                 float* __restrict__ out,
                 int B) {
    const int tid = threadIdx.x;
    const int lid = tid & 31;
    const int wid = tid >> 5;

    // ---------------- Phase A: one element, one packed atomic ----------------
    const int   idx = blockIdx.x * BLOCK + tid;
    const float p   = pred[idx];
    const int   t   = target[idx];
    const int   b   = bin_of(p);

    const long long q = (long long)llrintf(p * QSCALE);
    const unsigned long long pkt = (1ull << 48) + (unsigned long long)(q + BIAS);
    if (t == 1) atomicAdd(&g_posH[b], pkt);
    else        atomicAdd(&g_negH[b], pkt);

    // Trivial term: f32 elementwise (matches reference), double warp-reduce,
    // one fixed-point atomic per warp (deterministic).
    {
        double td = (double)(1.0f / (p * p + 1e-5f));
        #pragma unroll
        for (int off = 16; off > 0; off >>= 1)
            td += __shfl_down_sync(0xFFFFFFFFu, td, off);
        if (lid == 0)
            atomicAdd(&g_trivq, (unsigned long long)(long long)llrint(td * (double)QSCALE));
    }

    // ---------------- Ticket: last block does the tiny tail ----------------
    __shared__ bool s_last;
    __threadfence();
    __syncthreads();
    if (tid == 0) {
        const unsigned int old = atomicInc(&g_tick, (unsigned int)GRID - 1u);
        s_last = (old == (unsigned int)GRID - 1u);
    }
    __syncthreads();
    if (!s_last) return;

    // ---------------- Phase B: decode bins -> smem, self-zero globals --------
    __shared__ float s_pc[BINS];   // pos count per bin
    __shared__ float s_ps[BINS];   // pos sum per bin (dequantized)
    __shared__ float s_nc[BINS];   // neg count per bin
    __shared__ float s_ns[BINS];   // neg sum per bin
    #pragma unroll
    for (int i = tid; i < BINS; i += BLOCK) {        // 2 iterations
        const unsigned long long vp = g_posH[i];
        const unsigned long long vn = g_negH[i];
        g_posH[i] = 0ull;
        g_negH[i] = 0ull;
        const int pc = (int)(vp >> 48);
        const int nc = (int)(vn >> 48);
        const long long pq = (long long)(vp & MASK48) - (long long)pc * BIAS;
        const long long nq = (long long)(vn & MASK48) - (long long)nc * BIAS;
        s_pc[i] = (float)pc;
        s_ps[i] = (float)((double)pq * QINV_D);
        s_nc[i] = (float)nc;
        s_ns[i] = (float)((double)nq * QINV_D);
    }
    __syncthreads();

    // ---------------- One-warp suffix-scan evaluation ----------------
    if (wid == 0) {
        // Lane owns 16 consecutive bins [lid*16, lid*16+16)
        float pc_[16], ps_[16], nc_[16], ns_[16];
        float pcT = 0.f, psT = 0.f, ncT = 0.f;
        const int b0 = lid * 16;
        #pragma unroll
        for (int k = 0; k < 16; ++k) {
            pc_[k] = s_pc[b0 + k];  ps_[k] = s_ps[b0 + k];
            nc_[k] = s_nc[b0 + k];  ns_[k] = s_ns[b0 + k];
            pcT += pc_[k];  psT += ps_[k];  ncT += nc_[k];
        }

        // Inclusive suffix scan of lane totals (pos count / pos sum)
        float ipc = pcT, ips = psT;
        #pragma unroll
        for (int off = 1; off < 32; off <<= 1) {
            const float upc = __shfl_down_sync(0xFFFFFFFFu, ipc, off);
            const float ups = __shfl_down_sync(0xFFFFFFFFu, ips, off);
            if (lid + off < 32) { ipc += upc; ips += ups; }
        }
        const float n_pos = __shfl_sync(0xFFFFFFFFu, ipc, 0);   // total positives
        float runPC = ipc - pcT;   // strictly-above-lane offsets
        float runPS = ips - psT;

        // Serial within lane, high bin -> low bin
        double contrib = 0.0;
        #pragma unroll
        for (int k = 15; k >= 0; --k) {
            contrib += (double)nc_[k] * (double)runPS
                     - (double)ns_[k] * (double)runPC;
            runPC += pc_[k];
            runPS += ps_[k];
        }

        // Warp-reduce contribution and neg total
        double cn = (double)ncT;
        #pragma unroll
        for (int off = 16; off > 0; off >>= 1) {
            contrib += __shfl_down_sync(0xFFFFFFFFu, contrib, off);
            cn      += __shfl_down_sync(0xFFFFFFFFu, cn, off);
        }

        if (lid == 0) {
            const double triv = (double)(long long)g_trivq * QINV_D;
            g_trivq = 0ull;
            const double n_neg = cn;
            const double N = n_neg * (double)n_pos;
            out[0] = (float)(triv / (double)B + contrib / N);
        }
    }
}

extern "C" void kernel_launch(void* const* d_in, const int* in_sizes, int n_in,
                              void* d_out, int out_size) {
    const float* pred   = (const float*)d_in[0];
    const int*   target = (const int*)d_in[1];
    float*       out    = (float*)d_out;
    const int B = in_sizes[0];   // 8192

    rank_kernel<<<GRID, BLOCK>>>(pred, target, out, B);
}

// round 14
// speedup vs baseline: 1.0066x; 1.0066x over previous
#include <cuda_runtime.h>
#include <cuda_fp16.h>

// RankingLoss: out = mean(1/(pred^2+eps)) + [ sum_{i:neg, j:pos} relu(pred_j - pred_i) ] / (n_neg*n_pos)
// DELTA = 0, EPS = 1e-5, B = 8192. target is int32 on the wire.
//
// R8's winning shape (best measured: 12.8us) widened: grid (32, 32) = 1024 blocks,
// J_TILE = 256. Each block locally compacts the positives of its 256-wide j-tile
// into fp16 smem (sentinel -30000 padding to a 64-multiple) and runs the
// hfma2_relu inner loop (1 instr/pair) for its 256 i's. by==0 blocks also do the
// trivial term + neg count. Wrap-around ticket elects the last block for the
// final reduction (graph-replay safe).

#define BLOCK     256
#define J_TILE    256
#define GXB       32
#define GYB       32
#define NPART     (GXB * GYB)

__device__ double       g_pair[NPART];
__device__ double       g_triv[GXB];
__device__ int          g_negc[GXB];
__device__ unsigned int g_ticket;   // wraps -> self-resets every graph replay

__global__ __launch_bounds__(BLOCK)
void rank_fused_kernel(const float* __restrict__ pred,
                       const int* __restrict__ target,
                       float* __restrict__ out,
                       int B) {
    __shared__ __align__(16) __half spos[J_TILE + 64];
    __shared__ int swtot[BLOCK / 32];
    __shared__ int swoff[BLOCK / 32];
    __shared__ int s_npos;

    const int tid = threadIdx.x;
    const int lid = tid & 31;
    const int wid = tid >> 5;
    const int bx  = blockIdx.x;
    const int by  = blockIdx.y;
    const int j0  = by * J_TILE;

    // ---- Stage j-tile (1 element/thread) and flag positives ----
    const float pj = pred[j0 + tid];
    const int   tj = target[j0 + tid];
    const int   c0 = (tj == 1);

    // Warp-inclusive scan of the 0/1 flag
    int incl = c0;
    #pragma unroll
    for (int off = 1; off < 32; off <<= 1) {
        int v = __shfl_up_sync(0xFFFFFFFFu, incl, off);
        if (lid >= off) incl += v;
    }
    if (lid == 31) swtot[wid] = incl;
    __syncthreads();

    // Cross-warp scan (8 values) in warp 0
    if (wid == 0) {
        int v = (lid < BLOCK / 32) ? swtot[lid] : 0;
        int iv = v;
        #pragma unroll
        for (int off = 1; off < 8; off <<= 1) {
            int u = __shfl_up_sync(0xFFFFFFFFu, iv, off);
            if (lid >= off) iv += u;
        }
        if (lid < BLOCK / 32) swoff[lid] = iv - v;
        if (lid == BLOCK / 32 - 1) s_npos = iv;
    }
    __syncthreads();

    // Deterministic scatter of positives into compacted fp16 smem
    if (c0) spos[swoff[wid] + incl - 1] = __float2half_rn(pj);

    // Sentinel pad to a 64-multiple (64 halves = one inner window)
    const int npos = s_npos;
    const int npad = (npos + 63) & ~63;
    if (tid < npad - npos) spos[npos + tid] = __float2half_rn(-30000.0f);
    __syncthreads();

    // ---- i side: one i per thread ----
    const int i = bx * BLOCK + tid;
    const float pif = pred[i];
    const bool is_neg = (target[i] == 0);

    const __half2 npi2 = __float2half2_rn(-pif);
    const __half2 one2 = __float2half2_rn(1.0f);
    const __half2 z2   = __float2half2_rn(0.0f);
    const uint4* sp4 = reinterpret_cast<const uint4*>(spos);
    const int nq = npad >> 3;      // uint4 count, multiple of 8

    float facc = 0.0f;
    #pragma unroll 1
    for (int q = 0; q < nq; q += 8) {      // 64 j per window
        __half2 A = z2, C = z2;
        #pragma unroll
        for (int r = 0; r < 8; r += 2) {
            const uint4 u = sp4[q + r];
            const uint4 v = sp4[q + r + 1];
            A = __hadd2(A, __hfma2_relu(*(const __half2*)&u.x, one2, npi2));
            A = __hadd2(A, __hfma2_relu(*(const __half2*)&u.y, one2, npi2));
            A = __hadd2(A, __hfma2_relu(*(const __half2*)&u.z, one2, npi2));
            A = __hadd2(A, __hfma2_relu(*(const __half2*)&u.w, one2, npi2));
            C = __hadd2(C, __hfma2_relu(*(const __half2*)&v.x, one2, npi2));
            C = __hadd2(C, __hfma2_relu(*(const __half2*)&v.y, one2, npi2));
            C = __hadd2(C, __hfma2_relu(*(const __half2*)&v.z, one2, npi2));
            C = __hadd2(C, __hfma2_relu(*(const __half2*)&v.w, one2, npi2));
        }
        facc += (__low2float(A) + __high2float(A)) + (__low2float(C) + __high2float(C));
    }
    if (!is_neg) facc = 0.0f;

    // ---- Block reduce pair partial (double) ----
    double d = (double)facc;
    #pragma unroll
    for (int off = 16; off > 0; off >>= 1)
        d += __shfl_down_sync(0xFFFFFFFFu, d, off);
    __shared__ double wsum[BLOCK / 32];
    if (lid == 0) wsum[wid] = d;
    __syncthreads();
    if (wid == 0) {
        double t = (lid < BLOCK / 32) ? wsum[lid] : 0.0;
        #pragma unroll
        for (int off = 4; off > 0; off >>= 1)
            t += __shfl_down_sync(0xFFFFFFFFu, t, off);
        if (lid == 0) g_pair[by * GXB + bx] = t;
    }

    // ---- by==0 blocks: trivial term + neg count for this i-slab ----
    if (by == 0) {
        double td = (double)(1.0f / (pif * pif + 1e-5f));
        int    nc = is_neg ? 1 : 0;
        #pragma unroll
        for (int off = 16; off > 0; off >>= 1) {
            td += __shfl_down_sync(0xFFFFFFFFu, td, off);
            nc += __shfl_down_sync(0xFFFFFFFFu, nc, off);
        }
        __shared__ double twsum[BLOCK / 32];
        __shared__ int    nwsum[BLOCK / 32];
        if (lid == 0) { twsum[wid] = td; nwsum[wid] = nc; }
        __syncthreads();
        if (wid == 0) {
            double tt = (lid < BLOCK / 32) ? twsum[lid] : 0.0;
            int    nn = (lid < BLOCK / 32) ? nwsum[lid] : 0;
            #pragma unroll
            for (int off = 4; off > 0; off >>= 1) {
                tt += __shfl_down_sync(0xFFFFFFFFu, tt, off);
                nn += __shfl_down_sync(0xFFFFFFFFu, nn, off);
            }
            if (lid == 0) { g_triv[bx] = tt; g_negc[bx] = nn; }
        }
    }

    // ---- Last-block final reduction (ticket wraps -> graph-replay safe) ----
    __shared__ bool s_last;
    __threadfence();
    __syncthreads();
    if (tid == 0) {
        const unsigned int total = NPART;
        const unsigned int old = atomicInc(&g_ticket, total - 1u);
        s_last = (old == total - 1u);
    }
    __syncthreads();
    if (!s_last) return;

    double lp = 0.0, lt = 0.0;
    int    ln = 0;
    #pragma unroll
    for (int p = tid; p < NPART; p += BLOCK) lp += g_pair[p];
    if (tid < GXB) { lt = g_triv[tid]; ln = g_negc[tid]; }

    #pragma unroll
    for (int off = 16; off > 0; off >>= 1) {
        lp += __shfl_down_sync(0xFFFFFFFFu, lp, off);
        lt += __shfl_down_sync(0xFFFFFFFFu, lt, off);
        ln += __shfl_down_sync(0xFFFFFFFFu, ln, off);
    }
    __shared__ double fp[BLOCK / 32];
    __shared__ double ft[BLOCK / 32];
    __shared__ int    fn[BLOCK / 32];
    if (lid == 0) { fp[wid] = lp; ft[wid] = lt; fn[wid] = ln; }
    __syncthreads();
    if (tid == 0) {
        double sp = 0.0, st = 0.0;
        int    sn = 0;
        #pragma unroll
        for (int w = 0; w < BLOCK / 32; ++w) { sp += fp[w]; st += ft[w]; sn += fn[w]; }
        const double n_neg = (double)sn;
        const double n_pos = (double)B - n_neg;
        const double N = n_neg * n_pos;
        out[0] = (float)(st / (double)B + sp / N);
    }
}

extern "C" void kernel_launch(void* const* d_in, const int* in_sizes, int n_in,
                              void* d_out, int out_size) {
    const float* pred   = (const float*)d_in[0];
    const int*   target = (const int*)d_in[1];
    float*       out    = (float*)d_out;
    const int B = in_sizes[0];   // 8192

    dim3 grid(GXB, GYB);         // 1024 blocks
    rank_fused_kernel<<<grid, BLOCK>>>(pred, target, out, B);
}

// round 15
// speedup vs baseline: 1.3314x; 1.3227x over previous
#include <cuda_runtime.h>
#include <cuda_fp16.h>

// RankingLoss: out = mean(1/(pred^2+eps)) + [ sum_{i:neg, j:pos} relu(pred_j - pred_i) ] / (n_neg*n_pos)
// DELTA = 0, EPS = 1e-5, B = 8192. target is int32 on the wire.
//
// R8's best-measured body (512 blocks, local fp16 compaction of the j-tile,
// hfma2_relu inner loop) with a minimal serial tail:
//   - all cross-block reductions are fixed-point u64/int atomicAdds onto 3 scalars
//     (deterministic; quantization 2^-20 -> ~1e-10 relative error)
//   - __threadfence only on tid0 (atomicAdd -> fence -> ticket inc)
//   - last block: 3 atomicExch (read + self-zero for graph replay), compute, store.

#define BLOCK   256
#define J_TILE  512
#define GXB     32               // 8192 / 256 i per block
#define GYB     16               // 8192 / 512 j per tile
#define NPART   (GXB * GYB)
#define QSCALE  1048576.0        // 2^20
#define QINV    (1.0 / 1048576.0)

__device__ unsigned long long g_pairq;   // zero-init; atomicExch self-zeros each replay
__device__ unsigned long long g_trivq;
__device__ int                g_negc;
__device__ unsigned int       g_ticket;  // wraps -> self-resets every replay

__global__ __launch_bounds__(BLOCK)
void rank_fused_kernel(const float* __restrict__ pred,
                       const int* __restrict__ target,
                       float* __restrict__ out,
                       int B) {
    __shared__ __align__(16) __half spos[J_TILE + 64];
    __shared__ int swtot[BLOCK / 32];
    __shared__ int swoff[BLOCK / 32];
    __shared__ int s_npos;

    const int tid = threadIdx.x;
    const int lid = tid & 31;
    const int wid = tid >> 5;
    const int bx  = blockIdx.x;
    const int by  = blockIdx.y;
    const int j0  = by * J_TILE;

    // ---- Stage j-tile (2 elements/thread) and count positives ----
    const float2 pj = reinterpret_cast<const float2*>(pred + j0)[tid];
    const int2   tj = reinterpret_cast<const int2*>(target + j0)[tid];
    // i-side loads issued early too (overlap with scan)
    const int i = bx * BLOCK + tid;
    const float pif = pred[i];
    const bool is_neg = (target[i] == 0);

    const int c0 = (tj.x == 1);
    const int c1 = (tj.y == 1);
    const int cnt = c0 + c1;

    // Warp-inclusive scan of cnt
    int incl = cnt;
    #pragma unroll
    for (int off = 1; off < 32; off <<= 1) {
        int v = __shfl_up_sync(0xFFFFFFFFu, incl, off);
        if (lid >= off) incl += v;
    }
    if (lid == 31) swtot[wid] = incl;
    __syncthreads();

    // Cross-warp scan (8 values) in warp 0
    if (wid == 0) {
        int v = (lid < BLOCK / 32) ? swtot[lid] : 0;
        int iv = v;
        #pragma unroll
        for (int off = 1; off < 8; off <<= 1) {
            int u = __shfl_up_sync(0xFFFFFFFFu, iv, off);
            if (lid >= off) iv += u;
        }
        if (lid < BLOCK / 32) swoff[lid] = iv - v;
        if (lid == BLOCK / 32 - 1) s_npos = iv;
    }
    __syncthreads();

    // Deterministic scatter of positives into compacted fp16 smem
    {
        const int o = swoff[wid] + (incl - cnt);
        if (c0) spos[o] = __float2half_rn(pj.x);
        if (c1) spos[o + c0] = __float2half_rn(pj.y);
    }
    // Sentinel pad to a 64-multiple
    const int npos = s_npos;
    const int npad = (npos + 63) & ~63;
    if (tid < npad - npos) spos[npos + tid] = __float2half_rn(-30000.0f);
    __syncthreads();

    // ---- Inner loop: 1 i per thread over compacted positives ----
    const __half2 npi2 = __float2half2_rn(-pif);
    const __half2 one2 = __float2half2_rn(1.0f);
    const __half2 z2   = __float2half2_rn(0.0f);
    const uint4* sp4 = reinterpret_cast<const uint4*>(spos);
    const int nq = npad >> 3;          // uint4 count, multiple of 8

    float facc = 0.0f;
    #pragma unroll 1
    for (int q = 0; q < nq; q += 8) {  // 64 j per window
        __half2 A = z2, C = z2;
        #pragma unroll
        for (int r = 0; r < 8; r += 2) {
            const uint4 u = sp4[q + r];
            const uint4 v = sp4[q + r + 1];
            A = __hadd2(A, __hfma2_relu(*(const __half2*)&u.x, one2, npi2));
            A = __hadd2(A, __hfma2_relu(*(const __half2*)&u.y, one2, npi2));
            A = __hadd2(A, __hfma2_relu(*(const __half2*)&u.z, one2, npi2));
            A = __hadd2(A, __hfma2_relu(*(const __half2*)&u.w, one2, npi2));
            C = __hadd2(C, __hfma2_relu(*(const __half2*)&v.x, one2, npi2));
            C = __hadd2(C, __hfma2_relu(*(const __half2*)&v.y, one2, npi2));
            C = __hadd2(C, __hfma2_relu(*(const __half2*)&v.z, one2, npi2));
            C = __hadd2(C, __hfma2_relu(*(const __half2*)&v.w, one2, npi2));
        }
        facc += (__low2float(A) + __high2float(A)) + (__low2float(C) + __high2float(C));
    }
    if (!is_neg) facc = 0.0f;

    // ---- Block reduce pair partial (f32), tid0 emits ONE u64 atomic ----
    #pragma unroll
    for (int off = 16; off > 0; off >>= 1)
        facc += __shfl_down_sync(0xFFFFFFFFu, facc, off);
    __shared__ float wsum[BLOCK / 32];
    if (lid == 0) wsum[wid] = facc;
    __syncthreads();

    // ---- by==0 blocks: trivial term (double) + neg count ----
    double td = 0.0;
    int    nc = 0;
    if (by == 0) {
        td = (double)(1.0f / (pif * pif + 1e-5f));
        nc = is_neg ? 1 : 0;
        #pragma unroll
        for (int off = 16; off > 0; off >>= 1) {
            td += __shfl_down_sync(0xFFFFFFFFu, td, off);
            nc += __shfl_down_sync(0xFFFFFFFFu, nc, off);
        }
        __shared__ double twsum[BLOCK / 32];
        __shared__ int    nwsum[BLOCK / 32];
        if (lid == 0) { twsum[wid] = td; nwsum[wid] = nc; }
        __syncthreads();
        if (tid == 0) {
            double tt = 0.0; int nn = 0;
            #pragma unroll
            for (int w = 0; w < BLOCK / 32; ++w) { tt += twsum[w]; nn += nwsum[w]; }
            atomicAdd(&g_trivq, (unsigned long long)(long long)llrint(tt * QSCALE));
            atomicAdd(&g_negc, nn);
        }
    }

    // tid0: pair atomic -> fence -> ticket
    __shared__ bool s_last;
    if (tid == 0) {
        float bp = 0.0f;
        #pragma unroll
        for (int w = 0; w < BLOCK / 32; ++w) bp += wsum[w];
        atomicAdd(&g_pairq, (unsigned long long)(long long)llrint((double)bp * QSCALE));
        __threadfence();
        const unsigned int old = atomicInc(&g_ticket, (unsigned int)NPART - 1u);
        s_last = (old == (unsigned int)NPART - 1u);
    }
    __syncthreads();
    if (!s_last) return;

    // ---- Minimal tail: read + self-zero 3 scalars, compute, store ----
    if (tid == 0) {
        __threadfence();   // acquire: order scalar reads after all ticket arrivals
        const unsigned long long pq = atomicExch(&g_pairq, 0ull);
        const unsigned long long tq = atomicExch(&g_trivq, 0ull);
        const int                ng = atomicExch(&g_negc, 0);
        const double pair = (double)(long long)pq * QINV;
        const double triv = (double)(long long)tq * QINV;
        const double n_neg = (double)ng;
        const double n_pos = (double)B - n_neg;
        const double N = n_neg * n_pos;
        out[0] = (float)(triv / (double)B + pair / N);
    }
}

extern "C" void kernel_launch(void* const* d_in, const int* in_sizes, int n_in,
                              void* d_out, int out_size) {
    const float* pred   = (const float*)d_in[0];
    const int*   target = (const int*)d_in[1];
    float*       out    = (float*)d_out;
    const int B = in_sizes[0];   // 8192

    dim3 grid(GXB, GYB);         // 512 blocks
    rank_fused_kernel<<<grid, BLOCK>>>(pred, target, out, B);
}